// round 3
// baseline (speedup 1.0000x reference)
#include <cuda_runtime.h>
#include <cuda_bf16.h>

// StateSpaceLayer: out[b,t,r,c] = sum_{j<=t} A[r]^(t-j) * x[b,j,r,c]
// == per-(b,r,c) linear recurrence y_t = A[r]*y_{t-1} + x_t.
// x, out: (B,SEQ,D,D) fp32; A: (D,) fp32.  B=4, SEQ=512, D=64.
//
// R3: float2 vectorization + streaming cache hints + 1024-thread blocks.
// Block handles one full (b, r) row: 32 float2 c-lanes x 32 chunks of 16
// timesteps held in registers. Single-warp serial carry combine (a^16 steps).

#define SEQ   512
#define D     64
#define LCH   16            // timesteps per chunk (in registers, as float2)
#define NC    (SEQ/LCH)     // 32 chunks
#define CL2   32            // float2 c-lanes (covers all 64 c)
#define TPB   (NC*CL2)      // 1024 threads
#define TSTRIDE2 (D*D/2)    // timestep stride in float2 units = 2048

__global__ __launch_bounds__(TPB, 1)
void ssm_scan_kernel(const float2* __restrict__ x,
                     const float* __restrict__ A,
                     float2* __restrict__ out)
{
    // grid = B * D : one block per (b, r)
    const int bid = blockIdx.x;
    const int r   = bid & (D - 1);
    const int b   = bid >> 6;

    const int tid   = threadIdx.x;
    const int lane2 = tid & (CL2 - 1);   // float2 lane: c = 2*lane2, 2*lane2+1
    const int k     = tid >> 5;          // chunk index 0..NC-1

    const float a = fmaxf(A[r], 1e-6f);  // reference clips at EPS=1e-6

    // element (b, k*LCH + i, r, 2*lane2) as float2 index
    const long base = ((long)(b * SEQ + k * LCH) * D + r) * (D / 2) + lane2;
    const float2* __restrict__ xp = x + base;

    // ---- load chunk into registers: 16 independent streaming LDG.64 ----
    float2 v[LCH];
    #pragma unroll
    for (int i = 0; i < LCH; i++)
        v[i] = __ldcs(xp + (long)i * TSTRIDE2);

    // ---- local inclusive scan within chunk ----
    #pragma unroll
    for (int i = 1; i < LCH; i++) {
        v[i].x = fmaf(a, v[i - 1].x, v[i].x);
        v[i].y = fmaf(a, v[i - 1].y, v[i].y);
    }

    // ---- cross-chunk carry combine ----
    __shared__ float2 s_end[NC][CL2];
    __shared__ float2 s_pre[NC][CL2];
    s_end[k][lane2] = v[LCH - 1];
    __syncthreads();

    if (tid < CL2) {
        // a^16 via 4 squarings
        float a2  = a * a;
        float a4  = a2 * a2;
        float a8  = a4 * a4;
        float a16 = a8 * a8;
        float2 carry = make_float2(0.0f, 0.0f);
        #pragma unroll
        for (int kk = 0; kk < NC; kk++) {
            s_pre[kk][tid] = carry;                          // exclusive prefix
            float2 e = s_end[kk][tid];
            carry.x = fmaf(a16, carry.x, e.x);               // E_k = s_k + a^L * E_{k-1}
            carry.y = fmaf(a16, carry.y, e.y);
        }
    }
    __syncthreads();

    // ---- apply carry and store: out_i = v_i + a^(i+1) * E ----
    const float2 E = s_pre[k][lane2];
    float2* __restrict__ op = out + base;
    float pw = a;
    #pragma unroll
    for (int i = 0; i < LCH; i++) {
        float2 o;
        o.x = fmaf(pw, E.x, v[i].x);
        o.y = fmaf(pw, E.y, v[i].y);
        __stcs(op + (long)i * TSTRIDE2, o);
        pw *= a;
    }
}

extern "C" void kernel_launch(void* const* d_in, const int* in_sizes, int n_in,
                              void* d_out, int out_size)
{
    // Identify x vs A by element count (A has D=64 elements).
    const float* x = (const float*)d_in[0];
    const float* A = (const float*)d_in[1];
    long nx = in_sizes[0];
    if (n_in >= 2 && in_sizes[0] == D && in_sizes[1] > D) {
        x = (const float*)d_in[1];
        A = (const float*)d_in[0];
        nx = in_sizes[1];
    }
    const int B = (int)(nx / ((long)SEQ * D * D));   // 4

    dim3 grid(B * D);
    dim3 block(TPB);
    ssm_scan_kernel<<<grid, block>>>((const float2*)x, A, (float2*)d_out);
}